// round 3
// baseline (speedup 1.0000x reference)
#include <cuda_runtime.h>
#include <cstdint>

// ---------------------------------------------------------------------------
// APUNet as one GEMM: D[o,s] = sum_i G[o,i] * Xs[s,i] ; out = D + x
//   o = c*256 + hp*16 + wp (M=8192), s = n*64 + k*8 + j (N=1024), K=8192
// tf32 mma.sync (sm_80+ path; tcgen05 unavailable: harness targets sm_103).
// ---------------------------------------------------------------------------

#define MDIM 8192
#define NDIM 1024
#define KDIM 8192
#define BM 128
#define BN 256
#define BK 32
#define NCHUNK (KDIM / BK)      // 256
#define APITCH 36               // floats; bank = (4*row + col) % 32 -> conflict-free
#define ASTAGE (BM * APITCH)    // 4608 floats
#define BSTAGE (BN * APITCH)    // 9216 floats
#define SMEM_BYTES ((2 * ASTAGE + 3 * BSTAGE) * 4)   // 147456

__device__ float g_Xs[(size_t)NDIM * KDIM];   // 32 MB scratch: [s][i]

__device__ __forceinline__ uint32_t smem_u32(const void* p) {
    uint32_t a;
    asm("{ .reg .u64 t; cvta.to.shared.u64 t, %1; cvt.u32.u64 %0, t; }" : "=r"(a) : "l"(p));
    return a;
}
__device__ __forceinline__ uint32_t f2tf32(float v) {
    uint32_t u;
    asm("cvt.rna.tf32.f32 %0, %1;" : "=r"(u) : "f"(v));
    return u;
}

// ---------------------------------------------------------------------------
// im2col: x (16,32,128,128) -> Xs[s][i], values RNE-rounded to tf32
// ---------------------------------------------------------------------------
__global__ void __launch_bounds__(256) im2col_kernel(const float* __restrict__ x) {
    int b = blockIdx.x;                 // 16*32*16 = 8192 blocks: (n, c, hp)
    int hp = b & 15, c = (b >> 4) & 31, n = b >> 9;
    __shared__ float tile[1024];        // [k(8)][w(128)]
    const float* src = x + ((size_t)((n * 32 + c) * 128 + hp * 8)) * 128;
    int t = threadIdx.x;
#pragma unroll
    for (int r = 0; r < 4; r++) tile[t + r * 256] = src[t + r * 256];
    __syncthreads();
    int wp = t & 15;
    int ibase = c * 256 + hp * 16 + wp;
#pragma unroll
    for (int r = 0; r < 4; r++) {
        int sl = (t >> 4) + r * 16;     // 0..63 = k*8+j
        int k = sl >> 3, j = sl & 7;
        uint32_t u = f2tf32(tile[k * 128 + wp * 8 + j]);
        g_Xs[(size_t)(n * 64 + sl) * KDIM + ibase] = __uint_as_float(u);
    }
}

// ---------------------------------------------------------------------------
// GEMM: grid (4 n-blocks, 64 m-blocks), 256 threads, warps 2(M) x 4(N)
// ---------------------------------------------------------------------------
__global__ void __launch_bounds__(256, 1) gemm_kernel(
    const float* __restrict__ G, const float* __restrict__ x, float* __restrict__ out) {
    extern __shared__ float sm[];
    float* smA = sm;                    // 2 stages
    float* smB = sm + 2 * ASTAGE;       // 3 stages

    int t = threadIdx.x, lane = t & 31, wid = t >> 5;
    int wm = wid >> 2, wn = wid & 3;
    int m0 = blockIdx.y * BM, n0 = blockIdx.x * BN;
    const float* gbase = G + (size_t)m0 * KDIM;
    const float* bbase = g_Xs + (size_t)n0 * KDIM;

    float acc[4][8][4];
#pragma unroll
    for (int i = 0; i < 4; i++)
#pragma unroll
        for (int j = 0; j < 8; j++)
#pragma unroll
            for (int r = 0; r < 4; r++) acc[i][j][r] = 0.f;

    float4 aregs[4];

    auto ldgA = [&](int c) {
#pragma unroll
        for (int r = 0; r < 4; r++) {
            int v = t + r * 256;        // 1024 float4s: row = v>>3, c4 = v&7
            aregs[r] = *(const float4*)(gbase + (size_t)(v >> 3) * KDIM + c * BK + (v & 7) * 4);
        }
    };
    auto stsA = [&](int buf) {
#pragma unroll
        for (int r = 0; r < 4; r++) {
            int v = t + r * 256;
            float4 w;
            w.x = __uint_as_float(f2tf32(aregs[r].x));
            w.y = __uint_as_float(f2tf32(aregs[r].y));
            w.z = __uint_as_float(f2tf32(aregs[r].z));
            w.w = __uint_as_float(f2tf32(aregs[r].w));
            *(float4*)(smA + buf * ASTAGE + (v >> 3) * APITCH + (v & 7) * 4) = w;
        }
    };
    auto cpB = [&](int c) {
        float* base = smB + (c % 3) * BSTAGE;
#pragma unroll
        for (int r = 0; r < 8; r++) {
            int v = t + r * 256;        // 2048 float4s: row = v>>3, c4 = v&7
            uint32_t dst = smem_u32(base + (v >> 3) * APITCH + (v & 7) * 4);
            const float* src = bbase + (size_t)(v >> 3) * KDIM + c * BK + (v & 7) * 4;
            asm volatile("cp.async.cg.shared.global [%0], [%1], 16;" :: "r"(dst), "l"(src) : "memory");
        }
    };

    // prologue
    cpB(0); asm volatile("cp.async.commit_group;" ::: "memory");
    cpB(1); asm volatile("cp.async.commit_group;" ::: "memory");
    ldgA(0); stsA(0);
    ldgA(1);

#pragma unroll 1
    for (int c = 0; c < NCHUNK; c++) {
        asm volatile("cp.async.wait_group 1;" ::: "memory");
        __syncthreads();
        if (c + 2 < NCHUNK) cpB(c + 2);
        asm volatile("cp.async.commit_group;" ::: "memory");
        if (c + 1 < NCHUNK) stsA((c + 1) & 1);
        if (c + 2 < NCHUNK) ldgA(c + 2);

        const float* As = smA + (c & 1) * ASTAGE + (wm * 64 + (lane >> 2)) * APITCH + (lane & 3);
        const float* Bs = smB + (c % 3) * BSTAGE + (wn * 64 + (lane >> 2)) * APITCH + (lane & 3);
#pragma unroll
        for (int ks = 0; ks < 4; ks++) {
            uint32_t a[4][4], b[8][2];
#pragma unroll
            for (int i = 0; i < 4; i++) {
                const float* p = As + i * 16 * APITCH + ks * 8;
                a[i][0] = __float_as_uint(p[0]);
                a[i][1] = __float_as_uint(p[8 * APITCH]);
                a[i][2] = __float_as_uint(p[4]);
                a[i][3] = __float_as_uint(p[8 * APITCH + 4]);
            }
#pragma unroll
            for (int j = 0; j < 8; j++) {
                const float* p = Bs + j * 8 * APITCH + ks * 8;
                b[j][0] = __float_as_uint(p[0]);
                b[j][1] = __float_as_uint(p[4]);
            }
#pragma unroll
            for (int i = 0; i < 4; i++)
#pragma unroll
                for (int j = 0; j < 8; j++)
                    asm volatile(
                        "mma.sync.aligned.m16n8k8.row.col.f32.tf32.tf32.f32 "
                        "{%0,%1,%2,%3}, {%4,%5,%6,%7}, {%8,%9}, {%0,%1,%2,%3};"
                        : "+f"(acc[i][j][0]), "+f"(acc[i][j][1]),
                          "+f"(acc[i][j][2]), "+f"(acc[i][j][3])
                        : "r"(a[i][0]), "r"(a[i][1]), "r"(a[i][2]), "r"(a[i][3]),
                          "r"(b[j][0]), "r"(b[j][1]));
        }
    }

    // ---------------- epilogue: residual add + scatter store ----------------
    int lr = lane >> 2, lc2 = (lane & 3) * 2;
#pragma unroll
    for (int i = 0; i < 4; i++) {
#pragma unroll
        for (int half = 0; half < 2; half++) {
            int o = m0 + wm * 64 + i * 16 + lr + half * 8;
            int cch = o >> 8, p = o & 255, hp = p >> 4, wp = p & 15;
#pragma unroll
            for (int j = 0; j < 8; j++) {
                int s = n0 + wn * 64 + j * 8 + lc2;
                int n = s >> 6, k = (s >> 3) & 7;
                size_t idx = (((size_t)(n * 32 + cch) * 128) + hp * 8 + k) * 128 + wp * 8 + lc2;
                float2 xr = *(const float2*)(x + idx);
                float2 ov;
                ov.x = acc[i][j][half * 2 + 0] + xr.x;
                ov.y = acc[i][j][half * 2 + 1] + xr.y;
                *(float2*)(out + idx) = ov;
            }
        }
    }
}

// ---------------------------------------------------------------------------
extern "C" void kernel_launch(void* const* d_in, const int* in_sizes, int n_in,
                              void* d_out, int out_size) {
    const float* x = (const float*)d_in[0];   // 8,388,608 elems
    const float* g = (const float*)d_in[1];   // 67,108,864 elems
    if (in_sizes[0] > in_sizes[1]) { const float* tmp = x; x = g; g = tmp; }
    float* out = (float*)d_out;

    cudaFuncSetAttribute(gemm_kernel, cudaFuncAttributeMaxDynamicSharedMemorySize, SMEM_BYTES);
    im2col_kernel<<<8192, 256>>>(x);
    gemm_kernel<<<dim3(NDIM / BN, MDIM / BM), 256, SMEM_BYTES>>>(g, x, out);
}